// round 6
// baseline (speedup 1.0000x reference)
#include <cuda_runtime.h>
#include <math.h>

// Problem constants (fixed shapes from the reference)
#define B 128
#define C 512
#define HW 1024            // 32*32
#define E 16
#define KTOP 2
#define NOISE_STD_INV 16.0f   // 1 / (1/E) = E
#define TAU 1.0f
#define EPS 1e-8f

// Scratch (no allocations allowed in kernel_launch)
__device__ float g_pooled[B * C];
__device__ float g_logits[B * E];
__device__ int   g_cnt[B];      // per-batch-row arrival counters (self-reset)
__device__ int   g_done;        // GEMM-done counter (self-reset)

// ---------------------------------------------------------------------------
// One fused kernel, grid = 2048 x 256 threads (R1's proven pool shape).
//  - block k pools 32 contiguous (b,c) rows (warp: 4 rows), b = k/16
//  - 16th block to finish a row b does that row's 16-expert gate GEMM
//  - 128th GEMM block runs softmax/top-2/aux-loss finalize
// All float reductions are fixed-order -> bitwise deterministic per replay.
// ---------------------------------------------------------------------------
__global__ void __launch_bounds__(256, 8) fused_kernel(
        const float* __restrict__ x,
        const float* __restrict__ Wg,
        const float* __restrict__ complexity,
        const float* __restrict__ noise,
        float* __restrict__ out) {
    __shared__ int s_flag;

    const int tid  = threadIdx.x;
    const int w    = tid >> 5;        // 0..7
    const int lane = tid & 31;
    const int blk  = blockIdx.x;
    const int b    = blk >> 4;        // 16 blocks per batch row
    const int row0 = blk * 32 + w * 4;

    // ---- Phase 1: pool 4 rows per warp (coalesced float4 streaming).
#pragma unroll
    for (int i = 0; i < 4; ++i) {
        const float4* r = reinterpret_cast<const float4*>(x + (size_t)(row0 + i) * HW);
        float s = 0.0f;
#pragma unroll
        for (int j = 0; j < 8; ++j) {
            float4 v = __ldg(&r[lane + 32 * j]);
            s += (v.x + v.y) + (v.z + v.w);
        }
#pragma unroll
        for (int o = 16; o; o >>= 1) s += __shfl_xor_sync(0xffffffffu, s, o);
        if (lane == 0) g_pooled[row0 + i] = s * (1.0f / (float)HW);
    }

    // ---- Ticket 1: last block for row b does the GEMM.
    __threadfence();
    __syncthreads();
    if (tid == 0) s_flag = (atomicAdd(&g_cnt[b], 1) == 15);
    __syncthreads();
    if (!s_flag) return;
    __threadfence();   // acquire: other blocks' g_pooled writes

    // ---- Phase 2: gate GEMM for row b.  Warp w -> experts w and w+8.
    {
        const float* prow = g_pooled + b * C;
        const float* w0   = Wg + w * C;
        const float* w1   = Wg + (w + 8) * C;
        float s0 = 0.0f, s1 = 0.0f;
#pragma unroll
        for (int j = 0; j < C / 32; ++j) {
            int c = lane + 32 * j;    // coalesced
            float pv = prow[c];
            s0 = fmaf(pv, __ldg(&w0[c]), s0);
            s1 = fmaf(pv, __ldg(&w1[c]), s1);
        }
#pragma unroll
        for (int o = 16; o; o >>= 1) {
            s0 += __shfl_xor_sync(0xffffffffu, s0, o);
            s1 += __shfl_xor_sync(0xffffffffu, s1, o);
        }
        if (lane == 0) {
            g_logits[b * E + w]     = s0;
            g_logits[b * E + w + 8] = s1;
        }
    }
    if (tid == 0) g_cnt[b] = 0;       // reset for next graph replay

    // ---- Ticket 2: last GEMM block runs finalize.
    __threadfence();
    __syncthreads();
    if (tid == 0) s_flag = (atomicAdd(&g_done, 1) == B - 1);
    __syncthreads();
    if (!s_flag) return;
    __threadfence();   // acquire: all g_logits

    // ---- Phase 3 (one block, 256 threads): softmaxes, top-2, gates, loss.
    __shared__ float sm_clean[B][E];   // 8 KB
    __shared__ float sm_p[B][E];       // 8 KB
    __shared__ float sh_imp[E];
    __shared__ float sh_pm[E];

    const int bb = tid;
    if (bb < B) {
        float l[E], n[E];
#pragma unroll
        for (int e = 0; e < E; ++e) {
            l[e] = g_logits[bb * E + e];
            n[e] = l[e] + noise[bb * E + e];
        }
        // clean softmax
        {
            float mx = l[0];
#pragma unroll
            for (int e = 1; e < E; ++e) mx = fmaxf(mx, l[e]);
            float ssum = 0.0f, t2[E];
#pragma unroll
            for (int e = 0; e < E; ++e) { t2[e] = expf(l[e] - mx); ssum += t2[e]; }
            float inv = 1.0f / ssum;
#pragma unroll
            for (int e = 0; e < E; ++e) sm_clean[bb][e] = t2[e] * inv;
        }
        // noisy softmax
        float g[E];
        {
            float mx = n[0];
#pragma unroll
            for (int e = 1; e < E; ++e) mx = fmaxf(mx, n[e]);
            float ssum = 0.0f;
#pragma unroll
            for (int e = 0; e < E; ++e) { g[e] = expf(n[e] - mx); ssum += g[e]; }
            float inv = 1.0f / ssum;
#pragma unroll
            for (int e = 0; e < E; ++e) g[e] *= inv;
        }
        // top-2 (strict > => lowest index wins ties, matching jax.lax.top_k)
        int i1 = 0;
#pragma unroll
        for (int e = 1; e < E; ++e) if (g[e] > g[i1]) i1 = e;
        int i2 = (i1 == 0) ? 1 : 0;
#pragma unroll
        for (int e = 0; e < E; ++e) if (e != i1 && g[e] > g[i2]) i2 = e;
        float v1 = g[i1], v2 = g[i2];
        float thr = n[i2];   // 2nd-largest noisy logit

        // gates row + topk outputs
#pragma unroll
        for (int e = 0; e < E; ++e)
            out[bb * E + e] = (e == i1) ? v1 : ((e == i2) ? v2 : 0.0f);
        out[B * E + bb * KTOP + 0]            = (float)i1;
        out[B * E + bb * KTOP + 1]            = (float)i2;
        out[B * E + B * KTOP + bb * KTOP + 0] = v1;
        out[B * E + B * KTOP + bb * KTOP + 1] = v2;

        // p[e] = 1 - Phi((thr - l[e]) / sigma) = 0.5 * erfc(z / sqrt(2))
#pragma unroll
        for (int e = 0; e < E; ++e) {
            float z = (thr - l[e]) * NOISE_STD_INV;
            sm_p[bb][e] = 0.5f * erfcf(z * 0.70710678118654752f);
        }
    }
    __syncthreads();

    if (tid < E) {
        int e = tid;
        float si = 0.0f, sp = 0.0f;
        for (int r = 0; r < B; ++r) { si += sm_clean[r][e]; sp += sm_p[r][e]; }
        sh_imp[e] = si * (complexity[e] * TAU);
        sh_pm[e]  = sp * (1.0f / (float)B);
    }
    __syncthreads();

    if (tid == 0) {
        float mi = 0.0f, mp = 0.0f;
#pragma unroll
        for (int e = 0; e < E; ++e) { mi += sh_imp[e]; mp += sh_pm[e]; }
        mi *= (1.0f / (float)E);
        mp *= (1.0f / (float)E);
        float vi = 0.0f, vp = 0.0f;
#pragma unroll
        for (int e = 0; e < E; ++e) {
            float di = sh_imp[e] - mi; vi += di * di;
            float dp = sh_pm[e]  - mp; vp += dp * dp;
        }
        vi *= (1.0f / (float)(E - 1));   // ddof=1
        vp *= (1.0f / (float)(E - 1));
        float cvi = sqrtf(vi) / (mi + EPS);
        float cvp = sqrtf(vp) / (mp + EPS);
        out[B * E + 2 * B * KTOP] = 0.5f * (cvi * cvi) + 0.5f * (cvp * cvp);

        g_done = 0;   // reset ticket for next graph replay
    }
}

// ---------------------------------------------------------------------------
extern "C" void kernel_launch(void* const* d_in, const int* in_sizes, int n_in,
                              void* d_out, int out_size) {
    const float* x          = (const float*)d_in[0];
    const float* W_gate     = (const float*)d_in[1];
    const float* complexity = (const float*)d_in[2];
    const float* noise      = (const float*)d_in[3];
    float* out = (float*)d_out;

    // 2048 blocks x 256 threads: 16 blocks per batch row, warp pools 4 rows.
    fused_kernel<<<B * C / 32, 256>>>(x, W_gate, complexity, noise, out);
}

// round 10
// speedup vs baseline: 1.0064x; 1.0064x over previous
#include <cuda_runtime.h>
#include <math.h>

// Problem constants (fixed shapes from the reference)
#define B 128
#define C 512
#define HW 1024            // 32*32
#define E 16
#define KTOP 2
#define NOISE_STD_INV 16.0f   // 1 / (1/E) = E
#define TAU 1.0f
#define EPS 1e-8f

// Scratch (no allocations allowed in kernel_launch)
__device__ float g_pooled[B * C];   // 256 KB
__device__ float g_logits[B * E];
__device__ int   g_done;            // ticket, self-resetting each launch

// ---------------------------------------------------------------------------
// Kernel 1: adaptive avg pool.  One warp per (b,c) row of 1024 contiguous f32.
// EXACT copy of the R1 kernel measured at 83.9% DRAM / 41.1us.
// ---------------------------------------------------------------------------
__global__ void __launch_bounds__(256) pool_kernel(const float* __restrict__ x) {
    int gwarp = (blockIdx.x * blockDim.x + threadIdx.x) >> 5;
    int lane  = threadIdx.x & 31;

    const float4* row = reinterpret_cast<const float4*>(x + (size_t)gwarp * HW);
    float4 v[8];
#pragma unroll
    for (int j = 0; j < 8; ++j) v[j] = __ldg(&row[lane + 32 * j]);

    float s = 0.0f;
#pragma unroll
    for (int j = 0; j < 8; ++j) s += (v[j].x + v[j].y) + (v[j].z + v[j].w);

#pragma unroll
    for (int o = 16; o; o >>= 1) s += __shfl_xor_sync(0xffffffffu, s, o);
    if (lane == 0) g_pooled[gwarp] = s * (1.0f / (float)HW);
}

// ---------------------------------------------------------------------------
// Kernel 2: gate GEMM (grid=128, block b -> logits row b) + ticket-gated
// finalize (softmax/top-2/gates/aux loss) on the last-arriving block.
// All float reductions fixed-order -> bitwise deterministic per replay.
// ---------------------------------------------------------------------------
__global__ void __launch_bounds__(256) tail_kernel(
        const float* __restrict__ Wg,
        const float* __restrict__ complexity,
        const float* __restrict__ noise,
        float* __restrict__ out) {
    __shared__ int s_flag;

    const int tid  = threadIdx.x;
    const int w    = tid >> 5;        // 0..7
    const int lane = tid & 31;
    const int b    = blockIdx.x;

    // ---- GEMM for row b.  Warp w -> experts w and w+8, lanes over C.
    {
        const float* prow = g_pooled + b * C;
        const float* w0   = Wg + w * C;
        const float* w1   = Wg + (w + 8) * C;
        float s0 = 0.0f, s1 = 0.0f;
#pragma unroll
        for (int j = 0; j < C / 32; ++j) {
            int c = lane + 32 * j;    // coalesced
            float pv = __ldg(&prow[c]);
            s0 = fmaf(pv, __ldg(&w0[c]), s0);
            s1 = fmaf(pv, __ldg(&w1[c]), s1);
        }
#pragma unroll
        for (int o = 16; o; o >>= 1) {
            s0 += __shfl_xor_sync(0xffffffffu, s0, o);
            s1 += __shfl_xor_sync(0xffffffffu, s1, o);
        }
        if (lane == 0) {
            g_logits[b * E + w]     = s0;
            g_logits[b * E + w + 8] = s1;
        }
    }

    // ---- Ticket: last block runs finalize.
    __threadfence();
    __syncthreads();
    if (tid == 0) s_flag = (atomicAdd(&g_done, 1) == B - 1);
    __syncthreads();
    if (!s_flag) return;
    __threadfence();   // acquire: all blocks' g_logits

    // ---- Finalize (one block, 256 threads).
    __shared__ float sm_clean[B][E];   // 8 KB
    __shared__ float sm_p[B][E];       // 8 KB
    __shared__ float sh_imp[E];
    __shared__ float sh_pm[E];

    const int bb = tid;
    if (bb < B) {
        float l[E], n[E];
#pragma unroll
        for (int e = 0; e < E; ++e) {
            l[e] = g_logits[bb * E + e];
            n[e] = l[e] + noise[bb * E + e];
        }
        // clean softmax
        {
            float mx = l[0];
#pragma unroll
            for (int e = 1; e < E; ++e) mx = fmaxf(mx, l[e]);
            float ssum = 0.0f, t2[E];
#pragma unroll
            for (int e = 0; e < E; ++e) { t2[e] = expf(l[e] - mx); ssum += t2[e]; }
            float inv = 1.0f / ssum;
#pragma unroll
            for (int e = 0; e < E; ++e) sm_clean[bb][e] = t2[e] * inv;
        }
        // noisy softmax
        float g[E];
        {
            float mx = n[0];
#pragma unroll
            for (int e = 1; e < E; ++e) mx = fmaxf(mx, n[e]);
            float ssum = 0.0f;
#pragma unroll
            for (int e = 0; e < E; ++e) { g[e] = expf(n[e] - mx); ssum += g[e]; }
            float inv = 1.0f / ssum;
#pragma unroll
            for (int e = 0; e < E; ++e) g[e] *= inv;
        }
        // top-2 (strict > => lowest index wins ties, matching jax.lax.top_k)
        int i1 = 0;
#pragma unroll
        for (int e = 1; e < E; ++e) if (g[e] > g[i1]) i1 = e;
        int i2 = (i1 == 0) ? 1 : 0;
#pragma unroll
        for (int e = 0; e < E; ++e) if (e != i1 && g[e] > g[i2]) i2 = e;
        float v1 = g[i1], v2 = g[i2];
        float thr = n[i2];   // 2nd-largest noisy logit

        // gates row + topk outputs
#pragma unroll
        for (int e = 0; e < E; ++e)
            out[bb * E + e] = (e == i1) ? v1 : ((e == i2) ? v2 : 0.0f);
        out[B * E + bb * KTOP + 0]            = (float)i1;
        out[B * E + bb * KTOP + 1]            = (float)i2;
        out[B * E + B * KTOP + bb * KTOP + 0] = v1;
        out[B * E + B * KTOP + bb * KTOP + 1] = v2;

        // p[e] = 1 - Phi((thr - l[e]) / sigma) = 0.5 * erfc(z / sqrt(2))
#pragma unroll
        for (int e = 0; e < E; ++e) {
            float z = (thr - l[e]) * NOISE_STD_INV;
            sm_p[bb][e] = 0.5f * erfcf(z * 0.70710678118654752f);
        }
    }
    __syncthreads();

    if (tid < E) {
        int e = tid;
        float si = 0.0f, sp = 0.0f;
        for (int r = 0; r < B; ++r) { si += sm_clean[r][e]; sp += sm_p[r][e]; }
        sh_imp[e] = si * (complexity[e] * TAU);
        sh_pm[e]  = sp * (1.0f / (float)B);
    }
    __syncthreads();

    if (tid == 0) {
        float mi = 0.0f, mp = 0.0f;
#pragma unroll
        for (int e = 0; e < E; ++e) { mi += sh_imp[e]; mp += sh_pm[e]; }
        mi *= (1.0f / (float)E);
        mp *= (1.0f / (float)E);
        float vi = 0.0f, vp = 0.0f;
#pragma unroll
        for (int e = 0; e < E; ++e) {
            float di = sh_imp[e] - mi; vi += di * di;
            float dp = sh_pm[e]  - mp; vp += dp * dp;
        }
        vi *= (1.0f / (float)(E - 1));   // ddof=1
        vp *= (1.0f / (float)(E - 1));
        float cvi = sqrtf(vi) / (mi + EPS);
        float cvp = sqrtf(vp) / (mp + EPS);
        out[B * E + 2 * B * KTOP] = 0.5f * (cvi * cvi) + 0.5f * (cvp * cvp);

        g_done = 0;   // reset ticket for next graph replay
    }
}

// ---------------------------------------------------------------------------
extern "C" void kernel_launch(void* const* d_in, const int* in_sizes, int n_in,
                              void* d_out, int out_size) {
    const float* x          = (const float*)d_in[0];
    const float* W_gate     = (const float*)d_in[1];
    const float* complexity = (const float*)d_in[2];
    const float* noise      = (const float*)d_in[3];
    float* out = (float*)d_out;

    // 1 warp per (b,c) row; 8 warps per block -> 8192 blocks (proven shape)
    pool_kernel<<<B * C / 8, 256>>>(x);
    tail_kernel<<<B, 256>>>(W_gate, complexity, noise, out);
}